// round 9
// baseline (speedup 1.0000x reference)
#include <cuda_runtime.h>
#include <cstdint>

// x: (B=8, H=256, W=256, C=64) fp32, WIN=16, half=8
// out: (B, 961, 16*16*64) fp32, partition order (0,0),(0,8),(8,0),(8,8)
// windows per partition: 256, 240, 240, 225 -> 961 per batch
//
// R2 skeleton with 256-bit (v8.f32) global accesses, new on sm_100+:
// one block per window, 256 threads. Thread t covers the 32B chunk (t&127)
// of window-row 2i+(t>>7), i=0..7. 8 front-batched ld.global.nc.v8.f32
// (same in-flight bytes as R2's 16x16B) then 8 st.global.cs.v8.f32.
// Wider requests -> half the L1tex wavefronts per byte, longer contiguous
// runs per warp request presented to the DRAM scheduler.

#define NPB 961
#define IMG_ROW_BYTES 65536      // 256 cols * 64 ch * 4 B
#define WROW_BYTES    4096       // 16 cols * 64 ch * 4 B
#define WIN_BYTES     65536      // 16 rows * 4096 B

__global__ void __launch_bounds__(256, 2)
partition_kernel(const char* __restrict__ x, char* __restrict__ out)
{
    const int blk = blockIdx.x;            // b * 961 + p
    const int b   = blk / NPB;
    const int p   = blk - b * NPB;

    int r0, c0, nc, base;
    if (p < 256)      { r0 = 0; c0 = 0; nc = 16; base = 0;   }
    else if (p < 496) { r0 = 0; c0 = 8; nc = 15; base = 256; }
    else if (p < 736) { r0 = 8; c0 = 0; nc = 16; base = 496; }
    else              { r0 = 8; c0 = 8; nc = 15; base = 736; }

    const int q  = p - base;
    const int wr = q / nc;
    const int wc = q - wr * nc;
    const int row0 = r0 + wr * 16;
    const int col0 = c0 + wc * 16;

    const char* src = x
        + (size_t)(b * 256 + row0) * IMG_ROW_BYTES
        + (size_t)col0 * (64 * 4);
    char* dst = out + (size_t)blk * WIN_BYTES;

    const int t     = threadIdx.x;
    const int rsel  = t >> 7;              // 0 or 1: which row of the pair
    const int chunk = (t & 127) * 32;      // 32B chunk within the 4KB row

    float v[8][8];

    // Front-batch 8 independent 256-bit loads (rows 2i+rsel).
#pragma unroll
    for (int i = 0; i < 8; ++i) {
        const char* g = src + (size_t)(2 * i + rsel) * IMG_ROW_BYTES + chunk;
        asm volatile(
            "ld.global.nc.v8.f32 {%0,%1,%2,%3,%4,%5,%6,%7}, [%8];"
            : "=f"(v[i][0]), "=f"(v[i][1]), "=f"(v[i][2]), "=f"(v[i][3]),
              "=f"(v[i][4]), "=f"(v[i][5]), "=f"(v[i][6]), "=f"(v[i][7])
            : "l"(g));
    }

    // Drain with 8 streaming 256-bit stores.
#pragma unroll
    for (int i = 0; i < 8; ++i) {
        char* g = dst + (size_t)(2 * i + rsel) * WROW_BYTES + chunk;
        asm volatile(
            "st.global.cs.v8.f32 [%0], {%1,%2,%3,%4,%5,%6,%7,%8};"
            :: "l"(g),
               "f"(v[i][0]), "f"(v[i][1]), "f"(v[i][2]), "f"(v[i][3]),
               "f"(v[i][4]), "f"(v[i][5]), "f"(v[i][6]), "f"(v[i][7])
            : "memory");
    }
}

extern "C" void kernel_launch(void* const* d_in, const int* in_sizes, int n_in,
                              void* d_out, int out_size)
{
    const char* x = (const char*)d_in[0];
    char* out = (char*)d_out;
    partition_kernel<<<8 * NPB, 256>>>(x, out);
}

// round 11
// speedup vs baseline: 1.0522x; 1.0522x over previous
#include <cuda_runtime.h>
#include <cstdint>

// x: (B=8, H=256, W=256, C=64) fp32, WIN=16, half=8
// out: (B, 961, 16*16*64) fp32, partition order (0,0),(0,8),(8,0),(8,8)
// windows per partition: 256, 240, 240, 225 -> 961 per batch
//
// R2 skeleton + L2 eviction-priority shaping via createpolicy/cache_hint
// (direct .L2::evict_last on v4.f32 is rejected by sm_103a ptxas; the
// cache_hint form accepts 128-bit loads):
//   loads:  ld.global.nc.L2::cache_hint.v4.f32 with evict_last policy
//           -> pin the 134MB input in the 126MB L2 across graph replays
//   stores: st.global.cs (evict-first; 504MB pure streaming write)

#define Hh 256
#define Ww 256
#define Cc 64
#define NPB 961                // windows per batch
#define ROW_F4 (Ww * Cc / 4)   // float4 per input image row = 4096

__global__ void __launch_bounds__(256, 2)
partition_kernel(const float* __restrict__ x, float* __restrict__ out)
{
    const int blk = blockIdx.x;            // b * 961 + p
    const int b   = blk / NPB;
    const int p   = blk - b * NPB;

    int r0, c0, nc, base;
    if (p < 256)      { r0 = 0; c0 = 0; nc = 16; base = 0;   }
    else if (p < 496) { r0 = 0; c0 = 8; nc = 15; base = 256; }
    else if (p < 736) { r0 = 8; c0 = 0; nc = 16; base = 496; }
    else              { r0 = 8; c0 = 8; nc = 15; base = 736; }

    const int q  = p - base;
    const int wr = q / nc;
    const int wc = q - wr * nc;
    const int row0 = r0 + wr * 16;
    const int col0 = c0 + wc * 16;

    const float4* __restrict__ src =
        reinterpret_cast<const float4*>(x) +
        (size_t)(b * Hh + row0) * ROW_F4 + (size_t)col0 * (Cc / 4);
    float4* __restrict__ dst =
        reinterpret_cast<float4*>(out) + (size_t)blk * (16 * 16 * Cc / 4);

    const int t = threadIdx.x;             // 0..255: one float4 of the 4KB row

    // Evict-last policy for the input stream.
    uint64_t pol;
    asm("createpolicy.fractional.L2::evict_last.b64 %0, 1.0;" : "=l"(pol));

    // Front-batch ALL 16 independent LDG.128s (evict_last via cache_hint),
    // then drain with 16 streaming (evict_first) STG.128s.
    float4 v[16];
#pragma unroll
    for (int i = 0; i < 16; ++i) {
        const float4* g = &src[(size_t)i * ROW_F4 + t];
        asm volatile(
            "ld.global.nc.L2::cache_hint.v4.f32 {%0,%1,%2,%3}, [%4], %5;"
            : "=f"(v[i].x), "=f"(v[i].y), "=f"(v[i].z), "=f"(v[i].w)
            : "l"(g), "l"(pol));
    }
#pragma unroll
    for (int i = 0; i < 16; ++i)
        __stcs(&dst[i * 256 + t], v[i]);
}

extern "C" void kernel_launch(void* const* d_in, const int* in_sizes, int n_in,
                              void* d_out, int out_size)
{
    const float* x = (const float*)d_in[0];
    float* out = (float*)d_out;
    const int nblocks = 8 * NPB;           // 7688
    partition_kernel<<<nblocks, 256>>>(x, out);
}